// round 4
// baseline (speedup 1.0000x reference)
#include <cuda_runtime.h>
#include <cuda_bf16.h>
#include <math.h>
#include <stdint.h>

#define DIM  1024
#define HID  3072
#define MTOK 8192
#define FSCALE (1.0f/127.0f)
#define XQMAX 32512.0f            // 127*256
#define QH    4.0f                // fixed h quant scale
#define DSC   (1.0f/(4.0f*127.0f))

// ---------------- device scratch ----------------
__device__ __align__(16) int8_t g_x8h[(size_t)MTOK*DIM];
__device__ __align__(16) int8_t g_x8l[(size_t)MTOK*DIM];
__device__ __align__(16) int8_t g_wg8[(size_t)HID*DIM];
__device__ __align__(16) int8_t g_wu8[(size_t)HID*DIM];
__device__ __align__(16) int8_t g_wd8[(size_t)DIM*HID];
__device__ __align__(16) int8_t g_h8h[(size_t)MTOK*HID];
__device__ __align__(16) int8_t g_h8l[(size_t)MTOK*HID];
__device__ __align__(16) float  g_gf [(size_t)MTOK*HID];
__device__ __align__(16) float  g_uf [(size_t)MTOK*HID];
__device__ __align__(16) float  g_sx [MTOK];

// ---------------- helpers ----------------
__device__ __forceinline__ uint32_t smem_u32(const void* p){
    uint32_t a;
    asm("{ .reg .u64 t; cvta.to.shared.u64 t, %1; cvt.u32.u64 %0, t; }" : "=r"(a) : "l"(p));
    return a;
}
__device__ __forceinline__ void cp_async16(uint32_t s, const void* g){
    asm volatile("cp.async.cg.shared.global [%0], [%1], 16;" :: "r"(s), "l"(g));
}
#define CP_COMMIT() asm volatile("cp.async.commit_group;" ::: "memory")
#define CP_WAIT(N)  asm volatile("cp.async.wait_group %0;" :: "n"(N) : "memory")

__device__ __forceinline__ void ldsm_x4(uint32_t* r, uint32_t a){
    asm volatile("ldmatrix.sync.aligned.m8n8.x4.shared.b16 {%0,%1,%2,%3}, [%4];"
        : "=r"(r[0]),"=r"(r[1]),"=r"(r[2]),"=r"(r[3]) : "r"(a));
}
__device__ __forceinline__ void imma(int* d, const uint32_t* a, const uint32_t* b){
    asm volatile("mma.sync.aligned.m16n8k32.row.col.s32.s8.s8.s32 "
        "{%0,%1,%2,%3},{%4,%5,%6,%7},{%8,%9},{%0,%1,%2,%3};"
        : "+r"(d[0]),"+r"(d[1]),"+r"(d[2]),"+r"(d[3])
        : "r"(a[0]),"r"(a[1]),"r"(a[2]),"r"(a[3]), "r"(b[0]),"r"(b[1]));
}

// ---------------- prep: per-row int16 quantization of x ----------------
__global__ __launch_bounds__(256)
void k_quantx(const float* __restrict__ x, int8_t* __restrict__ xh,
              int8_t* __restrict__ xl, float* __restrict__ sx)
{
    __shared__ float wmax[8];
    const int row = blockIdx.x, tid = threadIdx.x;
    float4 v = ((const float4*)(x + (size_t)row*DIM))[tid];
    float m = fmaxf(fmaxf(fabsf(v.x), fabsf(v.y)), fmaxf(fabsf(v.z), fabsf(v.w)));
    #pragma unroll
    for (int o = 16; o > 0; o >>= 1) m = fmaxf(m, __shfl_xor_sync(0xffffffffu, m, o));
    if ((tid & 31) == 0) wmax[tid >> 5] = m;
    __syncthreads();
    if (tid < 8){
        float t = wmax[tid];
        #pragma unroll
        for (int o = 4; o > 0; o >>= 1) t = fmaxf(t, __shfl_xor_sync(0xffu, t, o));
        if (tid == 0) wmax[0] = fmaxf(t, 1e-30f);
    }
    __syncthreads();
    const float rmax = wmax[0];
    const float qs = XQMAX / rmax;
    int q0 = __float2int_rn(v.x*qs), q1 = __float2int_rn(v.y*qs);
    int q2 = __float2int_rn(v.z*qs), q3 = __float2int_rn(v.w*qs);
    int h0=(q0+128)>>8, h1=(q1+128)>>8, h2=(q2+128)>>8, h3=(q3+128)>>8;
    char4 ch = make_char4((char)h0,(char)h1,(char)h2,(char)h3);
    char4 cl = make_char4((char)(q0-(h0<<8)),(char)(q1-(h1<<8)),
                          (char)(q2-(h2<<8)),(char)(q3-(h3<<8)));
    ((char4*)(xh + (size_t)row*DIM))[tid] = ch;
    ((char4*)(xl + (size_t)row*DIM))[tid] = cl;
    if (tid == 0) sx[row] = rmax / (XQMAX * 127.0f);
}

// ---------------- prep: int32 weights -> s8 ----------------
__global__ void k_convw8(const int* __restrict__ w, int8_t* __restrict__ o, int n4){
    int i = blockIdx.x * blockDim.x + threadIdx.x;
    if (i < n4){
        int4 v = ((const int4*)w)[i];
        ((char4*)o)[i] = make_char4((char)v.x,(char)v.y,(char)v.z,(char)v.w);
    }
}

// ---------------- swiglu + int16 quant of h ----------------
__global__ __launch_bounds__(256)
void k_swiglu(const float* __restrict__ g, const float* __restrict__ u,
              int8_t* __restrict__ hh, int8_t* __restrict__ hl, int n4)
{
    int i = blockIdx.x * blockDim.x + threadIdx.x;
    if (i < n4){
        float4 gv = ((const float4*)g)[i];
        float4 uv = ((const float4*)u)[i];
        float h0 = gv.x / (1.0f + __expf(-gv.x)) * uv.x;
        float h1 = gv.y / (1.0f + __expf(-gv.y)) * uv.y;
        float h2 = gv.z / (1.0f + __expf(-gv.z)) * uv.z;
        float h3 = gv.w / (1.0f + __expf(-gv.w)) * uv.w;
        int q0 = __float2int_rn(fminf(fmaxf(h0*QH, -XQMAX), XQMAX));
        int q1 = __float2int_rn(fminf(fmaxf(h1*QH, -XQMAX), XQMAX));
        int q2 = __float2int_rn(fminf(fmaxf(h2*QH, -XQMAX), XQMAX));
        int q3 = __float2int_rn(fminf(fmaxf(h3*QH, -XQMAX), XQMAX));
        int a0=(q0+128)>>8, a1=(q1+128)>>8, a2=(q2+128)>>8, a3=(q3+128)>>8;
        ((char4*)hh)[i] = make_char4((char)a0,(char)a1,(char)a2,(char)a3);
        ((char4*)hl)[i] = make_char4((char)(q0-(a0<<8)),(char)(q1-(a1<<8)),
                                     (char)(q2-(a2<<8)),(char)(q3-(a3<<8)));
    }
}

// ---------------- shared GEMM config ----------------
// CTA tile 128x128, 512 thr (16 warps, 4x4), warp tile 32x32, BK=64 s8.
static constexpr int ROWB  = 80;             // 64 data + 16 pad
static constexpr int AHI_O = 0;
static constexpr int ALO_O = 128*ROWB;       // 10240
static constexpr int B_O   = 2*128*ROWB;     // 20480
static constexpr int STG   = B_O + 128*ROWB; // 30720
static constexpr int NST   = 4;              // 122880 smem

// GEMM core macro body: computes int accs over K, from s8 planes.
// k_gateup_one: out_f[r*HID+c] = (256*acch+accl) * sx[r]   (z picks wg/g or wu/u)
__global__ __launch_bounds__(512,1)
void k_proj_gu(const int8_t* __restrict__ ah, const int8_t* __restrict__ al,
               const int8_t* __restrict__ wg, const int8_t* __restrict__ wu,
               const float* __restrict__ sx,
               float* __restrict__ gf, float* __restrict__ uf)
{
    const int8_t* bsrc = blockIdx.z ? wu : wg;
    float* dst = blockIdx.z ? uf : gf;

    extern __shared__ char sm[];
    const uint32_t sb = smem_u32(sm);
    const int tid = threadIdx.x, lane = tid & 31, wid = tid >> 5;
    const int wm = wid >> 2, wn = wid & 3;
    const int m0 = blockIdx.y * 128, n0 = blockIdx.x * 128;

    const int8_t* gptr[3];
    uint32_t soff[3];
    #pragma unroll
    for (int j = 0; j < 3; ++j){
        int c = j*512 + tid;
        int row = c >> 2, seg = c & 3;
        const int8_t* gp; uint32_t so;
        if (row < 128)      { gp = ah   + (size_t)(m0+row)*DIM;     so = AHI_O + row*ROWB; }
        else if (row < 256) { gp = al   + (size_t)(m0+row-128)*DIM; so = ALO_O + (row-128)*ROWB; }
        else                { gp = bsrc + (size_t)(n0+row-256)*DIM; so = B_O   + (row-256)*ROWB; }
        gptr[j] = gp + seg*16;
        soff[j] = so + seg*16;
    }
    auto load_stage = [&](int s){
        uint32_t st = sb + (uint32_t)(s & (NST-1)) * STG;
        int k0 = s * 64;
        #pragma unroll
        for (int j = 0; j < 3; ++j) cp_async16(st + soff[j], gptr[j] + k0);
    };

    int acch[2][4][4], accl[2][4][4];
    #pragma unroll
    for (int a=0;a<2;++a)
    #pragma unroll
    for (int b=0;b<4;++b)
    #pragma unroll
    for (int c=0;c<4;++c){ acch[a][b][c]=0; accl[a][b][c]=0; }

    load_stage(0); CP_COMMIT();
    load_stage(1); CP_COMMIT();
    load_stage(2); CP_COMMIT();

    const int arow = (lane & 7) + ((lane >> 3) & 1) * 8;
    const int akb  = ((lane >> 4) & 1) * 16;
    const int brow = (lane & 7) + ((lane >> 4) & 1) * 8;
    const int bkb  = ((lane >> 3) & 1) * 16;

    const int S = DIM / 64;   // 16
    for (int s = 0; s < S; ++s){
        CP_WAIT(2);
        __syncthreads();
        if (s + 3 < S) load_stage(s + 3);
        CP_COMMIT();

        uint32_t st = sb + (uint32_t)(s & (NST-1)) * STG;
        #pragma unroll
        for (int ks = 0; ks < 2; ++ks){
            uint32_t ahf[2][4], alf[2][4];
            #pragma unroll
            for (int mt = 0; mt < 2; ++mt){
                uint32_t aa = st + (uint32_t)((wm*32 + mt*16 + arow)*ROWB + ks*32 + akb);
                ldsm_x4(ahf[mt], aa + AHI_O);
                ldsm_x4(alf[mt], aa + ALO_O);
            }
            uint32_t bf[4][2];
            #pragma unroll
            for (int p = 0; p < 2; ++p){
                uint32_t ba = st + B_O + (uint32_t)((wn*32 + p*16 + brow)*ROWB + ks*32 + bkb);
                uint32_t t[4];
                ldsm_x4(t, ba);
                bf[2*p][0]=t[0]; bf[2*p][1]=t[1]; bf[2*p+1][0]=t[2]; bf[2*p+1][1]=t[3];
            }
            #pragma unroll
            for (int mt = 0; mt < 2; ++mt)
            #pragma unroll
            for (int nt = 0; nt < 4; ++nt){
                imma(acch[mt][nt], ahf[mt], bf[nt]);
                imma(accl[mt][nt], alf[mt], bf[nt]);
            }
        }
    }

    const int gl = lane >> 2, tig = lane & 3;
    #pragma unroll
    for (int mt = 0; mt < 2; ++mt){
        #pragma unroll
        for (int rr = 0; rr < 2; ++rr){
            int r = m0 + wm*32 + mt*16 + gl + rr*8;
            float s = sx[r];
            #pragma unroll
            for (int nt = 0; nt < 4; ++nt){
                int col = n0 + wn*32 + nt*8 + tig*2;
                float2 o;
                o.x = (256.0f*(float)acch[mt][nt][rr*2+0] + (float)accl[mt][nt][rr*2+0]) * s;
                o.y = (256.0f*(float)acch[mt][nt][rr*2+1] + (float)accl[mt][nt][rr*2+1]) * s;
                *(float2*)(dst + (size_t)r*HID + col) = o;
            }
        }
    }
}

// down: out[r*DIM+c] = (256*acch+accl) * DSC,  K = HID
__global__ __launch_bounds__(512,1)
void k_down(const int8_t* __restrict__ ah, const int8_t* __restrict__ al,
            const int8_t* __restrict__ wd, float* __restrict__ out)
{
    extern __shared__ char sm[];
    const uint32_t sb = smem_u32(sm);
    const int tid = threadIdx.x, lane = tid & 31, wid = tid >> 5;
    const int wm = wid >> 2, wn = wid & 3;
    const int m0 = blockIdx.y * 128, n0 = blockIdx.x * 128;

    const int8_t* gptr[3];
    uint32_t soff[3];
    #pragma unroll
    for (int j = 0; j < 3; ++j){
        int c = j*512 + tid;
        int row = c >> 2, seg = c & 3;
        const int8_t* gp; uint32_t so;
        if (row < 128)      { gp = ah + (size_t)(m0+row)*HID;     so = AHI_O + row*ROWB; }
        else if (row < 256) { gp = al + (size_t)(m0+row-128)*HID; so = ALO_O + (row-128)*ROWB; }
        else                { gp = wd + (size_t)(n0+row-256)*HID; so = B_O   + (row-256)*ROWB; }
        gptr[j] = gp + seg*16;
        soff[j] = so + seg*16;
    }
    auto load_stage = [&](int s){
        uint32_t st = sb + (uint32_t)(s & (NST-1)) * STG;
        int k0 = s * 64;
        #pragma unroll
        for (int j = 0; j < 3; ++j) cp_async16(st + soff[j], gptr[j] + k0);
    };

    int acch[2][4][4], accl[2][4][4];
    #pragma unroll
    for (int a=0;a<2;++a)
    #pragma unroll
    for (int b=0;b<4;++b)
    #pragma unroll
    for (int c=0;c<4;++c){ acch[a][b][c]=0; accl[a][b][c]=0; }

    load_stage(0); CP_COMMIT();
    load_stage(1); CP_COMMIT();
    load_stage(2); CP_COMMIT();

    const int arow = (lane & 7) + ((lane >> 3) & 1) * 8;
    const int akb  = ((lane >> 4) & 1) * 16;
    const int brow = (lane & 7) + ((lane >> 4) & 1) * 8;
    const int bkb  = ((lane >> 3) & 1) * 16;

    const int S = HID / 64;   // 48
    for (int s = 0; s < S; ++s){
        CP_WAIT(2);
        __syncthreads();
        if (s + 3 < S) load_stage(s + 3);
        CP_COMMIT();

        uint32_t st = sb + (uint32_t)(s & (NST-1)) * STG;
        #pragma unroll
        for (int ks = 0; ks < 2; ++ks){
            uint32_t ahf[2][4], alf[2][4];
            #pragma unroll
            for (int mt = 0; mt < 2; ++mt){
                uint32_t aa = st + (uint32_t)((wm*32 + mt*16 + arow)*ROWB + ks*32 + akb);
                ldsm_x4(ahf[mt], aa + AHI_O);
                ldsm_x4(alf[mt], aa + ALO_O);
            }
            uint32_t bf[4][2];
            #pragma unroll
            for (int p = 0; p < 2; ++p){
                uint32_t ba = st + B_O + (uint32_t)((wn*32 + p*16 + brow)*ROWB + ks*32 + bkb);
                uint32_t t[4];
                ldsm_x4(t, ba);
                bf[2*p][0]=t[0]; bf[2*p][1]=t[1]; bf[2*p+1][0]=t[2]; bf[2*p+1][1]=t[3];
            }
            #pragma unroll
            for (int mt = 0; mt < 2; ++mt)
            #pragma unroll
            for (int nt = 0; nt < 4; ++nt){
                imma(acch[mt][nt], ahf[mt], bf[nt]);
                imma(accl[mt][nt], alf[mt], bf[nt]);
            }
        }
    }

    const int gl = lane >> 2, tig = lane & 3;
    #pragma unroll
    for (int mt = 0; mt < 2; ++mt){
        #pragma unroll
        for (int rr = 0; rr < 2; ++rr){
            int r = m0 + wm*32 + mt*16 + gl + rr*8;
            #pragma unroll
            for (int nt = 0; nt < 4; ++nt){
                int col = n0 + wn*32 + nt*8 + tig*2;
                float2 o;
                o.x = (256.0f*(float)acch[mt][nt][rr*2+0] + (float)accl[mt][nt][rr*2+0]) * DSC;
                o.y = (256.0f*(float)acch[mt][nt][rr*2+1] + (float)accl[mt][nt][rr*2+1]) * DSC;
                *(float2*)(out + (size_t)r*DIM + col) = o;
            }
        }
    }
}

// ---------------- launch ----------------
extern "C" void kernel_launch(void* const* d_in, const int* in_sizes, int n_in,
                              void* d_out, int out_size)
{
    const float* x  = (const float*)d_in[0];
    const int*   wg = (const int*)d_in[1];
    const int*   wu = (const int*)d_in[2];
    const int*   wd = (const int*)d_in[3];
    float*       out = (float*)d_out;

    const int M = in_sizes[0] / DIM;   // 8192

    int8_t *x8h,*x8l,*wg8,*wu8,*wd8,*h8h,*h8l;
    float *gf,*uf,*sx;
    cudaGetSymbolAddress((void**)&x8h, g_x8h);
    cudaGetSymbolAddress((void**)&x8l, g_x8l);
    cudaGetSymbolAddress((void**)&wg8, g_wg8);
    cudaGetSymbolAddress((void**)&wu8, g_wu8);
    cudaGetSymbolAddress((void**)&wd8, g_wd8);
    cudaGetSymbolAddress((void**)&h8h, g_h8h);
    cudaGetSymbolAddress((void**)&h8l, g_h8l);
    cudaGetSymbolAddress((void**)&gf,  g_gf);
    cudaGetSymbolAddress((void**)&uf,  g_uf);
    cudaGetSymbolAddress((void**)&sx,  g_sx);

    // prep
    k_quantx<<<M, 256>>>(x, x8h, x8l, sx);
    {
        int n4 = (HID * DIM) / 4;
        k_convw8<<<(n4 + 255) / 256, 256>>>(wg, wg8, n4);
        k_convw8<<<(n4 + 255) / 256, 256>>>(wu, wu8, n4);
        k_convw8<<<(n4 + 255) / 256, 256>>>(wd, wd8, n4);
    }

    const int SMB = NST * STG;   // 122880
    cudaFuncSetAttribute(k_proj_gu, cudaFuncAttributeMaxDynamicSharedMemorySize, SMB);
    cudaFuncSetAttribute(k_down,    cudaFuncAttributeMaxDynamicSharedMemorySize, SMB);

    dim3 g1(HID / 128, M / 128, 2);   // (24, 64, 2)
    k_proj_gu<<<g1, 512, SMB>>>(x8h, x8l, wg8, wu8, sx, gf, uf);

    int n4 = (M * HID) / 4;
    k_swiglu<<<(n4 + 255) / 256, 256>>>(gf, uf, h8h, h8l, n4);

    dim3 g3(DIM / 128, M / 128);      // (8, 64)
    k_down<<<g3, 512, SMB>>>(h8h, h8l, wd8, out);
}

// round 5
// speedup vs baseline: 2.6173x; 2.6173x over previous
#include <cuda_runtime.h>
#include <cuda_bf16.h>
#include <math.h>
#include <stdint.h>

#define DIM  1024
#define HID  3072
#define MTOK 8192
#define FSCALE (1.0f/127.0f)

// ---------------- device scratch ----------------
__device__ __align__(16) __nv_bfloat16 g_wg [(size_t)HID*DIM];
__device__ __align__(16) __nv_bfloat16 g_wu [(size_t)HID*DIM];
__device__ __align__(16) __nv_bfloat16 g_wd [(size_t)DIM*HID];
__device__ __align__(16) __nv_bfloat16 g_xhi[(size_t)MTOK*DIM];
__device__ __align__(16) __nv_bfloat16 g_xlo[(size_t)MTOK*DIM];
__device__ __align__(16) __nv_bfloat16 g_hhi[(size_t)MTOK*HID];
__device__ __align__(16) __nv_bfloat16 g_hlo[(size_t)MTOK*HID];

// ---------------- helpers ----------------
__device__ __forceinline__ uint32_t smem_u32(const void* p){
    uint32_t a;
    asm("{ .reg .u64 t; cvta.to.shared.u64 t, %1; cvt.u32.u64 %0, t; }" : "=r"(a) : "l"(p));
    return a;
}
__device__ __forceinline__ void cp_async16(uint32_t s, const void* g){
    asm volatile("cp.async.cg.shared.global [%0], [%1], 16;" :: "r"(s), "l"(g));
}
#define CP_COMMIT() asm volatile("cp.async.commit_group;" ::: "memory")
#define CP_WAIT(N)  asm volatile("cp.async.wait_group %0;" :: "n"(N) : "memory")

__device__ __forceinline__ void ldsm_x4(uint32_t* r, uint32_t a){
    asm volatile("ldmatrix.sync.aligned.m8n8.x4.shared.b16 {%0,%1,%2,%3}, [%4];"
        : "=r"(r[0]),"=r"(r[1]),"=r"(r[2]),"=r"(r[3]) : "r"(a));
}
__device__ __forceinline__ void mma16816(float* d, const uint32_t* a, const uint32_t* b){
    asm volatile("mma.sync.aligned.m16n8k16.row.col.f32.bf16.bf16.f32 "
        "{%0,%1,%2,%3},{%4,%5,%6,%7},{%8,%9},{%0,%1,%2,%3};"
        : "+f"(d[0]),"+f"(d[1]),"+f"(d[2]),"+f"(d[3])
        : "r"(a[0]),"r"(a[1]),"r"(a[2]),"r"(a[3]), "r"(b[0]),"r"(b[1]));
}

// ---------------- prep kernels ----------------
__global__ void k_convw(const int* __restrict__ w, __nv_bfloat16* __restrict__ o, int n4){
    int i = blockIdx.x * blockDim.x + threadIdx.x;
    if (i < n4){
        int4 v = ((const int4*)w)[i];
        __nv_bfloat162 a, b;
        a.x = __float2bfloat16((float)v.x); a.y = __float2bfloat16((float)v.y);
        b.x = __float2bfloat16((float)v.z); b.y = __float2bfloat16((float)v.w);
        ((__nv_bfloat162*)o)[2*i]   = a;
        ((__nv_bfloat162*)o)[2*i+1] = b;
    }
}
__global__ void k_splitx(const float* __restrict__ x, __nv_bfloat16* __restrict__ hi,
                         __nv_bfloat16* __restrict__ lo, int n4){
    int i = blockIdx.x * blockDim.x + threadIdx.x;
    if (i < n4){
        float4 v = ((const float4*)x)[i];
        __nv_bfloat162 h0, h1, l0, l1;
        h0.x = __float2bfloat16(v.x); h0.y = __float2bfloat16(v.y);
        h1.x = __float2bfloat16(v.z); h1.y = __float2bfloat16(v.w);
        l0.x = __float2bfloat16(v.x - __bfloat162float(h0.x));
        l0.y = __float2bfloat16(v.y - __bfloat162float(h0.y));
        l1.x = __float2bfloat16(v.z - __bfloat162float(h1.x));
        l1.y = __float2bfloat16(v.w - __bfloat162float(h1.y));
        ((__nv_bfloat162*)hi)[2*i]   = h0; ((__nv_bfloat162*)hi)[2*i+1] = h1;
        ((__nv_bfloat162*)lo)[2*i]   = l0; ((__nv_bfloat162*)lo)[2*i+1] = l1;
    }
}

// ---------------- GEMM config ----------------
// CTA 128x128 (gateup: x2 outputs), 512 thr = 16 warps (4x4), warp tile 32x32.
// BK=64 (128B data rows + 16B pad = 144B stride, conflict-free ldmatrix).
static constexpr int ROWB  = 144;
static constexpr int AHI_O = 0;
static constexpr int ALO_O = 128*ROWB;          // 18432
static constexpr int B_O   = 2*128*ROWB;        // 36864
static constexpr int STG1  = B_O + 256*ROWB;    // 73728 (A hi/lo + Wg + Wu)
static constexpr int STG3  = B_O + 128*ROWB;    // 55296 (A hi/lo + Wd)
static constexpr int NST   = 3;

// ---------------- GEMM1: fused gate/up + SwiGLU ----------------
__global__ __launch_bounds__(512,1)
void k_gateup(const __nv_bfloat16* __restrict__ xhi, const __nv_bfloat16* __restrict__ xlo,
              const __nv_bfloat16* __restrict__ wg,  const __nv_bfloat16* __restrict__ wu,
              __nv_bfloat16* __restrict__ hhi, __nv_bfloat16* __restrict__ hlo)
{
    extern __shared__ char sm[];
    const uint32_t sb = smem_u32(sm);
    const int tid = threadIdx.x, lane = tid & 31, wid = tid >> 5;
    const int wm = wid >> 2, wn = wid & 3;
    const int m0 = blockIdx.y * 128, n0 = blockIdx.x * 128;

    // 8 cp.async chunks of 16B per thread per stage (512 rows x 128B)
    const __nv_bfloat16* gptr[8];
    uint32_t soff[8];
    #pragma unroll
    for (int j = 0; j < 8; ++j){
        int c = j*512 + tid;          // 0..4095
        int row = c >> 3, seg = c & 7;
        const __nv_bfloat16* gp; uint32_t so;
        if (row < 128)      { gp = xhi + (size_t)(m0+row)*DIM;     so = AHI_O + row*ROWB; }
        else if (row < 256) { gp = xlo + (size_t)(m0+row-128)*DIM; so = ALO_O + (row-128)*ROWB; }
        else if (row < 384) { gp = wg  + (size_t)(n0+row-256)*DIM; so = B_O   + (row-256)*ROWB; }
        else                { gp = wu  + (size_t)(n0+row-384)*DIM; so = B_O   + (row-256)*ROWB; }
        gptr[j] = gp + seg*8;
        soff[j] = so + seg*16;
    }
    auto load_stage = [&](int s){
        uint32_t st = sb + (uint32_t)(s % NST) * STG1;
        int k0 = s * 64;
        #pragma unroll
        for (int j = 0; j < 8; ++j) cp_async16(st + soff[j], gptr[j] + k0);
        CP_COMMIT();
    };

    float accg[2][4][4], accu[2][4][4];
    #pragma unroll
    for (int a = 0; a < 2; ++a)
    #pragma unroll
    for (int b = 0; b < 4; ++b)
    #pragma unroll
    for (int c = 0; c < 4; ++c){ accg[a][b][c] = 0.f; accu[a][b][c] = 0.f; }

    load_stage(0);
    load_stage(1);

    const int arow  = lane & 15;
    const int abyte = (lane >> 4) * 16;
    const int brow  = ((lane >> 4) & 1) * 8 + (lane & 7);
    const int bbyte = ((lane >> 3) & 1) * 16;

    const int S = DIM / 64;   // 16
    for (int s = 0; s < S; ++s){
        CP_WAIT(1);
        __syncthreads();
        if (s + 2 < S) load_stage(s + 2);

        uint32_t st = sb + (uint32_t)(s % NST) * STG1;
        #pragma unroll
        for (int ks = 0; ks < 4; ++ks){
            uint32_t ah[2][4], al[2][4];
            #pragma unroll
            for (int mt = 0; mt < 2; ++mt){
                uint32_t aaddr = st + (uint32_t)((wm*32 + mt*16 + arow)*ROWB + ks*32 + abyte);
                ldsm_x4(ah[mt], aaddr + AHI_O);
                ldsm_x4(al[mt], aaddr + ALO_O);
            }
            uint32_t bg[4][2], bu[4][2];
            #pragma unroll
            for (int p = 0; p < 2; ++p){
                uint32_t baddr = st + B_O + (uint32_t)((wn*32 + p*16 + brow)*ROWB + ks*32 + bbyte);
                uint32_t t[4];
                ldsm_x4(t, baddr);
                bg[2*p][0]=t[0]; bg[2*p][1]=t[1]; bg[2*p+1][0]=t[2]; bg[2*p+1][1]=t[3];
                ldsm_x4(t, baddr + 128*ROWB);
                bu[2*p][0]=t[0]; bu[2*p][1]=t[1]; bu[2*p+1][0]=t[2]; bu[2*p+1][1]=t[3];
            }
            // hi pass (no acc touched twice within 16 MMAs)
            #pragma unroll
            for (int mt = 0; mt < 2; ++mt)
            #pragma unroll
            for (int nt = 0; nt < 4; ++nt){
                mma16816(accg[mt][nt], ah[mt], bg[nt]);
                mma16816(accu[mt][nt], ah[mt], bu[nt]);
            }
            // lo pass
            #pragma unroll
            for (int mt = 0; mt < 2; ++mt)
            #pragma unroll
            for (int nt = 0; nt < 4; ++nt){
                mma16816(accg[mt][nt], al[mt], bg[nt]);
                mma16816(accu[mt][nt], al[mt], bu[nt]);
            }
        }
    }

    // epilogue: h = silu(gate)*up, split hi/lo bf16
    const int g = lane >> 2, tig = lane & 3;
    #pragma unroll
    for (int mt = 0; mt < 2; ++mt){
        int rb = m0 + wm*32 + mt*16 + g;
        #pragma unroll
        for (int nt = 0; nt < 4; ++nt){
            int col = n0 + wn*32 + nt*8 + tig*2;
            #pragma unroll
            for (int rr = 0; rr < 2; ++rr){
                int r = rb + rr*8;
                float g0 = accg[mt][nt][rr*2+0] * FSCALE;
                float g1 = accg[mt][nt][rr*2+1] * FSCALE;
                float u0 = accu[mt][nt][rr*2+0] * FSCALE;
                float u1 = accu[mt][nt][rr*2+1] * FSCALE;
                float h0 = g0 / (1.0f + __expf(-g0)) * u0;
                float h1 = g1 / (1.0f + __expf(-g1)) * u1;
                __nv_bfloat162 ph, pl;
                ph.x = __float2bfloat16(h0); ph.y = __float2bfloat16(h1);
                pl.x = __float2bfloat16(h0 - __bfloat162float(ph.x));
                pl.y = __float2bfloat16(h1 - __bfloat162float(ph.y));
                *(__nv_bfloat162*)(hhi + (size_t)r*HID + col) = ph;
                *(__nv_bfloat162*)(hlo + (size_t)r*HID + col) = pl;
            }
        }
    }
}

// ---------------- GEMM3: out = SCALE * h @ Wd^T ----------------
__global__ __launch_bounds__(512,1)
void k_down(const __nv_bfloat16* __restrict__ ahi, const __nv_bfloat16* __restrict__ alo,
            const __nv_bfloat16* __restrict__ wd, float* __restrict__ out)
{
    extern __shared__ char sm[];
    const uint32_t sb = smem_u32(sm);
    const int tid = threadIdx.x, lane = tid & 31, wid = tid >> 5;
    const int wm = wid >> 2, wn = wid & 3;
    const int m0 = blockIdx.y * 128, n0 = blockIdx.x * 128;

    // 6 chunks per thread per stage (384 rows x 128B)
    const __nv_bfloat16* gptr[6];
    uint32_t soff[6];
    #pragma unroll
    for (int j = 0; j < 6; ++j){
        int c = j*512 + tid;          // 0..3071
        int row = c >> 3, seg = c & 7;
        const __nv_bfloat16* gp; uint32_t so;
        if (row < 128)      { gp = ahi + (size_t)(m0+row)*HID;     so = AHI_O + row*ROWB; }
        else if (row < 256) { gp = alo + (size_t)(m0+row-128)*HID; so = ALO_O + (row-128)*ROWB; }
        else                { gp = wd  + (size_t)(n0+row-256)*HID; so = B_O   + (row-256)*ROWB; }
        gptr[j] = gp + seg*8;
        soff[j] = so + seg*16;
    }
    auto load_stage = [&](int s){
        uint32_t st = sb + (uint32_t)(s % NST) * STG3;
        int k0 = s * 64;
        #pragma unroll
        for (int j = 0; j < 6; ++j) cp_async16(st + soff[j], gptr[j] + k0);
        CP_COMMIT();
    };

    float acc[2][4][4];
    #pragma unroll
    for (int a = 0; a < 2; ++a)
    #pragma unroll
    for (int b = 0; b < 4; ++b)
    #pragma unroll
    for (int c = 0; c < 4; ++c) acc[a][b][c] = 0.f;

    load_stage(0);
    load_stage(1);

    const int arow  = lane & 15;
    const int abyte = (lane >> 4) * 16;
    const int brow  = ((lane >> 4) & 1) * 8 + (lane & 7);
    const int bbyte = ((lane >> 3) & 1) * 16;

    const int S = HID / 64;   // 48
    for (int s = 0; s < S; ++s){
        CP_WAIT(1);
        __syncthreads();
        if (s + 2 < S) load_stage(s + 2);

        uint32_t st = sb + (uint32_t)(s % NST) * STG3;
        #pragma unroll
        for (int ks = 0; ks < 4; ++ks){
            uint32_t ah[2][4], al[2][4];
            #pragma unroll
            for (int mt = 0; mt < 2; ++mt){
                uint32_t aaddr = st + (uint32_t)((wm*32 + mt*16 + arow)*ROWB + ks*32 + abyte);
                ldsm_x4(ah[mt], aaddr + AHI_O);
                ldsm_x4(al[mt], aaddr + ALO_O);
            }
            uint32_t bw[4][2];
            #pragma unroll
            for (int p = 0; p < 2; ++p){
                uint32_t baddr = st + B_O + (uint32_t)((wn*32 + p*16 + brow)*ROWB + ks*32 + bbyte);
                uint32_t t[4];
                ldsm_x4(t, baddr);
                bw[2*p][0]=t[0]; bw[2*p][1]=t[1]; bw[2*p+1][0]=t[2]; bw[2*p+1][1]=t[3];
            }
            #pragma unroll
            for (int mt = 0; mt < 2; ++mt)
            #pragma unroll
            for (int nt = 0; nt < 4; ++nt)
                mma16816(acc[mt][nt], ah[mt], bw[nt]);
            #pragma unroll
            for (int mt = 0; mt < 2; ++mt)
            #pragma unroll
            for (int nt = 0; nt < 4; ++nt)
                mma16816(acc[mt][nt], al[mt], bw[nt]);
        }
    }

    const int g = lane >> 2, tig = lane & 3;
    #pragma unroll
    for (int mt = 0; mt < 2; ++mt){
        int rb = m0 + wm*32 + mt*16 + g;
        #pragma unroll
        for (int nt = 0; nt < 4; ++nt){
            int col = n0 + wn*32 + nt*8 + tig*2;
            #pragma unroll
            for (int rr = 0; rr < 2; ++rr){
                int r = rb + rr*8;
                float2 o;
                o.x = acc[mt][nt][rr*2+0] * FSCALE;
                o.y = acc[mt][nt][rr*2+1] * FSCALE;
                *(float2*)(out + (size_t)r*DIM + col) = o;
            }
        }
    }
}

// ---------------- launch ----------------
extern "C" void kernel_launch(void* const* d_in, const int* in_sizes, int n_in,
                              void* d_out, int out_size)
{
    const float* x  = (const float*)d_in[0];
    const int*   wg = (const int*)d_in[1];
    const int*   wu = (const int*)d_in[2];
    const int*   wd = (const int*)d_in[3];
    float*       out = (float*)d_out;

    const int M = in_sizes[0] / DIM;   // 8192

    __nv_bfloat16 *wgb, *wub, *wdb, *xhi, *xlo, *hhi, *hlo;
    cudaGetSymbolAddress((void**)&wgb, g_wg);
    cudaGetSymbolAddress((void**)&wub, g_wu);
    cudaGetSymbolAddress((void**)&wdb, g_wd);
    cudaGetSymbolAddress((void**)&xhi, g_xhi);
    cudaGetSymbolAddress((void**)&xlo, g_xlo);
    cudaGetSymbolAddress((void**)&hhi, g_hhi);
    cudaGetSymbolAddress((void**)&hlo, g_hlo);

    {
        int n4 = (HID * DIM) / 4;
        k_convw<<<(n4 + 255) / 256, 256>>>(wg, wgb, n4);
        k_convw<<<(n4 + 255) / 256, 256>>>(wu, wub, n4);
        k_convw<<<(n4 + 255) / 256, 256>>>(wd, wdb, n4);
        int nx4 = (M * DIM) / 4;
        k_splitx<<<(nx4 + 255) / 256, 256>>>(x, xhi, xlo, nx4);
    }

    const int SM1 = NST * STG1;   // 221184
    const int SM3 = NST * STG3;   // 165888
    cudaFuncSetAttribute(k_gateup, cudaFuncAttributeMaxDynamicSharedMemorySize, SM1);
    cudaFuncSetAttribute(k_down,   cudaFuncAttributeMaxDynamicSharedMemorySize, SM3);

    dim3 g1(HID / 128, M / 128);   // (24, 64)
    k_gateup<<<g1, 512, SM1>>>(xhi, xlo, wgb, wub, hhi, hlo);

    dim3 g3(DIM / 128, M / 128);   // (8, 64)
    k_down<<<g3, 512, SM3>>>(hhi, hlo, wdb, out);
}

// round 6
// speedup vs baseline: 2.7355x; 1.0451x over previous
#include <cuda_runtime.h>
#include <cuda_bf16.h>
#include <math.h>
#include <stdint.h>

#define DIM  1024
#define HID  3072
#define MTOK 8192
#define FSCALE (1.0f/127.0f)

// ---------------- device scratch ----------------
__device__ __align__(16) __nv_bfloat16 g_wg [(size_t)HID*DIM];
__device__ __align__(16) __nv_bfloat16 g_wu [(size_t)HID*DIM];
__device__ __align__(16) __nv_bfloat16 g_wd [(size_t)DIM*HID];
__device__ __align__(16) __nv_bfloat16 g_xhi[(size_t)MTOK*DIM];
__device__ __align__(16) __nv_bfloat16 g_xlo[(size_t)MTOK*DIM];
__device__ __align__(16) __nv_bfloat16 g_hhi[(size_t)MTOK*HID];
__device__ __align__(16) __nv_bfloat16 g_hlo[(size_t)MTOK*HID];

// ---------------- helpers ----------------
__device__ __forceinline__ uint32_t smem_u32(const void* p){
    uint32_t a;
    asm("{ .reg .u64 t; cvta.to.shared.u64 t, %1; cvt.u32.u64 %0, t; }" : "=r"(a) : "l"(p));
    return a;
}
__device__ __forceinline__ void cp_async16(uint32_t s, const void* g){
    asm volatile("cp.async.cg.shared.global [%0], [%1], 16;" :: "r"(s), "l"(g));
}
#define CP_COMMIT() asm volatile("cp.async.commit_group;" ::: "memory")
#define CP_WAIT(N)  asm volatile("cp.async.wait_group %0;" :: "n"(N) : "memory")

__device__ __forceinline__ void ldsm_x4(uint32_t* r, uint32_t a){
    asm volatile("ldmatrix.sync.aligned.m8n8.x4.shared.b16 {%0,%1,%2,%3}, [%4];"
        : "=r"(r[0]),"=r"(r[1]),"=r"(r[2]),"=r"(r[3]) : "r"(a));
}
__device__ __forceinline__ void mma16816(float* d, const uint32_t* a, const uint32_t* b){
    asm volatile("mma.sync.aligned.m16n8k16.row.col.f32.bf16.bf16.f32 "
        "{%0,%1,%2,%3},{%4,%5,%6,%7},{%8,%9},{%0,%1,%2,%3};"
        : "+f"(d[0]),"+f"(d[1]),"+f"(d[2]),"+f"(d[3])
        : "r"(a[0]),"r"(a[1]),"r"(a[2]),"r"(a[3]), "r"(b[0]),"r"(b[1]));
}

// ---------------- prep kernels ----------------
__global__ void k_convw(const int* __restrict__ w, __nv_bfloat16* __restrict__ o, int n4){
    int i = blockIdx.x * blockDim.x + threadIdx.x;
    if (i < n4){
        int4 v = ((const int4*)w)[i];
        __nv_bfloat162 a, b;
        a.x = __float2bfloat16((float)v.x); a.y = __float2bfloat16((float)v.y);
        b.x = __float2bfloat16((float)v.z); b.y = __float2bfloat16((float)v.w);
        ((__nv_bfloat162*)o)[2*i]   = a;
        ((__nv_bfloat162*)o)[2*i+1] = b;
    }
}
__global__ void k_splitx(const float* __restrict__ x, __nv_bfloat16* __restrict__ hi,
                         __nv_bfloat16* __restrict__ lo, int n4){
    int i = blockIdx.x * blockDim.x + threadIdx.x;
    if (i < n4){
        float4 v = ((const float4*)x)[i];
        __nv_bfloat162 h0, h1, l0, l1;
        h0.x = __float2bfloat16(v.x); h0.y = __float2bfloat16(v.y);
        h1.x = __float2bfloat16(v.z); h1.y = __float2bfloat16(v.w);
        l0.x = __float2bfloat16(v.x - __bfloat162float(h0.x));
        l0.y = __float2bfloat16(v.y - __bfloat162float(h0.y));
        l1.x = __float2bfloat16(v.z - __bfloat162float(h1.x));
        l1.y = __float2bfloat16(v.w - __bfloat162float(h1.y));
        ((__nv_bfloat162*)hi)[2*i]   = h0; ((__nv_bfloat162*)hi)[2*i+1] = h1;
        ((__nv_bfloat162*)lo)[2*i]   = l0; ((__nv_bfloat162*)lo)[2*i+1] = l1;
    }
}

// ---------------- GEMM config ----------------
// BK=64 (128B data rows + 16B pad = 144B stride, conflict-free ldmatrix).
static constexpr int ROWB  = 144;
static constexpr int AHI_O = 0;
static constexpr int ALO_O = 128*ROWB;          // 18432
static constexpr int B_O   = 2*128*ROWB;        // 36864
static constexpr int STG1  = B_O + 256*ROWB;    // 73728 (A hi/lo + Wg + Wu)
static constexpr int STG3  = B_O + 256*ROWB;    // 73728 (A hi/lo + Wd 256 rows)
static constexpr int NST   = 3;

// ---------------- GEMM1: fused gate/up + SwiGLU ----------------
// CTA 128m x (128 gate + 128 up), 16 warps 4x4, warp 32 x (32g+32u).
__global__ __launch_bounds__(512,1)
void k_gateup(const __nv_bfloat16* __restrict__ xhi, const __nv_bfloat16* __restrict__ xlo,
              const __nv_bfloat16* __restrict__ wg,  const __nv_bfloat16* __restrict__ wu,
              __nv_bfloat16* __restrict__ hhi, __nv_bfloat16* __restrict__ hlo)
{
    extern __shared__ char sm[];
    const uint32_t sb = smem_u32(sm);
    const int tid = threadIdx.x, lane = tid & 31, wid = tid >> 5;
    const int wm = wid >> 2, wn = wid & 3;
    const int m0 = blockIdx.y * 128, n0 = blockIdx.x * 128;

    const __nv_bfloat16* gptr[8];
    uint32_t soff[8];
    #pragma unroll
    for (int j = 0; j < 8; ++j){
        int c = j*512 + tid;          // 0..4095
        int row = c >> 3, seg = c & 7;
        const __nv_bfloat16* gp; uint32_t so;
        if (row < 128)      { gp = xhi + (size_t)(m0+row)*DIM;     so = AHI_O + row*ROWB; }
        else if (row < 256) { gp = xlo + (size_t)(m0+row-128)*DIM; so = ALO_O + (row-128)*ROWB; }
        else if (row < 384) { gp = wg  + (size_t)(n0+row-256)*DIM; so = B_O   + (row-256)*ROWB; }
        else                { gp = wu  + (size_t)(n0+row-384)*DIM; so = B_O   + (row-256)*ROWB; }
        gptr[j] = gp + seg*8;
        soff[j] = so + seg*16;
    }
    auto load_stage = [&](int s){
        uint32_t st = sb + (uint32_t)(s % NST) * STG1;
        int k0 = s * 64;
        #pragma unroll
        for (int j = 0; j < 8; ++j) cp_async16(st + soff[j], gptr[j] + k0);
        CP_COMMIT();
    };

    float accg[2][4][4], accu[2][4][4];
    #pragma unroll
    for (int a = 0; a < 2; ++a)
    #pragma unroll
    for (int b = 0; b < 4; ++b)
    #pragma unroll
    for (int c = 0; c < 4; ++c){ accg[a][b][c] = 0.f; accu[a][b][c] = 0.f; }

    load_stage(0);
    load_stage(1);

    const int arow  = lane & 15;
    const int abyte = (lane >> 4) * 16;
    const int brow  = ((lane >> 4) & 1) * 8 + (lane & 7);
    const int bbyte = ((lane >> 3) & 1) * 16;

    const int S = DIM / 64;   // 16
    for (int s = 0; s < S; ++s){
        CP_WAIT(1);
        __syncthreads();
        if (s + 2 < S) load_stage(s + 2);

        uint32_t st = sb + (uint32_t)(s % NST) * STG1;
        #pragma unroll
        for (int ks = 0; ks < 4; ++ks){
            uint32_t ah[2][4], al[2][4];
            #pragma unroll
            for (int mt = 0; mt < 2; ++mt){
                uint32_t aaddr = st + (uint32_t)((wm*32 + mt*16 + arow)*ROWB + ks*32 + abyte);
                ldsm_x4(ah[mt], aaddr + AHI_O);
                ldsm_x4(al[mt], aaddr + ALO_O);
            }
            uint32_t bg[4][2], bu[4][2];
            #pragma unroll
            for (int p = 0; p < 2; ++p){
                uint32_t baddr = st + B_O + (uint32_t)((wn*32 + p*16 + brow)*ROWB + ks*32 + bbyte);
                uint32_t t[4];
                ldsm_x4(t, baddr);
                bg[2*p][0]=t[0]; bg[2*p][1]=t[1]; bg[2*p+1][0]=t[2]; bg[2*p+1][1]=t[3];
                ldsm_x4(t, baddr + 128*ROWB);
                bu[2*p][0]=t[0]; bu[2*p][1]=t[1]; bu[2*p+1][0]=t[2]; bu[2*p+1][1]=t[3];
            }
            #pragma unroll
            for (int mt = 0; mt < 2; ++mt)
            #pragma unroll
            for (int nt = 0; nt < 4; ++nt){
                mma16816(accg[mt][nt], ah[mt], bg[nt]);
                mma16816(accu[mt][nt], ah[mt], bu[nt]);
            }
            #pragma unroll
            for (int mt = 0; mt < 2; ++mt)
            #pragma unroll
            for (int nt = 0; nt < 4; ++nt){
                mma16816(accg[mt][nt], al[mt], bg[nt]);
                mma16816(accu[mt][nt], al[mt], bu[nt]);
            }
        }
    }

    const int g = lane >> 2, tig = lane & 3;
    #pragma unroll
    for (int mt = 0; mt < 2; ++mt){
        int rb = m0 + wm*32 + mt*16 + g;
        #pragma unroll
        for (int nt = 0; nt < 4; ++nt){
            int col = n0 + wn*32 + nt*8 + tig*2;
            #pragma unroll
            for (int rr = 0; rr < 2; ++rr){
                int r = rb + rr*8;
                float g0 = accg[mt][nt][rr*2+0] * FSCALE;
                float g1 = accg[mt][nt][rr*2+1] * FSCALE;
                float u0 = accu[mt][nt][rr*2+0] * FSCALE;
                float u1 = accu[mt][nt][rr*2+1] * FSCALE;
                float h0 = g0 / (1.0f + __expf(-g0)) * u0;
                float h1 = g1 / (1.0f + __expf(-g1)) * u1;
                __nv_bfloat162 ph, pl;
                ph.x = __float2bfloat16(h0); ph.y = __float2bfloat16(h1);
                pl.x = __float2bfloat16(h0 - __bfloat162float(ph.x));
                pl.y = __float2bfloat16(h1 - __bfloat162float(ph.y));
                *(__nv_bfloat162*)(hhi + (size_t)r*HID + col) = ph;
                *(__nv_bfloat162*)(hlo + (size_t)r*HID + col) = pl;
            }
        }
    }
}

// ---------------- GEMM3: out = SCALE * h @ Wd^T ----------------
// CTA 128m x 256n, 16 warps 4x4, warp tile 32 x 64.
__global__ __launch_bounds__(512,1)
void k_down(const __nv_bfloat16* __restrict__ ahi, const __nv_bfloat16* __restrict__ alo,
            const __nv_bfloat16* __restrict__ wd, float* __restrict__ out)
{
    extern __shared__ char sm[];
    const uint32_t sb = smem_u32(sm);
    const int tid = threadIdx.x, lane = tid & 31, wid = tid >> 5;
    const int wm = wid >> 2, wn = wid & 3;
    const int m0 = blockIdx.y * 128, n0 = blockIdx.x * 256;

    // 512 rows x 128B per stage: Ahi 128, Alo 128, Wd 256.
    const __nv_bfloat16* gptr[8];
    uint32_t soff[8];
    #pragma unroll
    for (int j = 0; j < 8; ++j){
        int c = j*512 + tid;          // 0..4095
        int row = c >> 3, seg = c & 7;
        const __nv_bfloat16* gp; uint32_t so;
        if (row < 128)      { gp = ahi + (size_t)(m0+row)*HID;     so = AHI_O + row*ROWB; }
        else if (row < 256) { gp = alo + (size_t)(m0+row-128)*HID; so = ALO_O + (row-128)*ROWB; }
        else                { gp = wd  + (size_t)(n0+row-256)*HID; so = B_O   + (row-256)*ROWB; }
        gptr[j] = gp + seg*8;
        soff[j] = so + seg*16;
    }
    auto load_stage = [&](int s){
        uint32_t st = sb + (uint32_t)(s % NST) * STG3;
        int k0 = s * 64;
        #pragma unroll
        for (int j = 0; j < 8; ++j) cp_async16(st + soff[j], gptr[j] + k0);
        CP_COMMIT();
    };

    float acc[2][8][4];
    #pragma unroll
    for (int a = 0; a < 2; ++a)
    #pragma unroll
    for (int b = 0; b < 8; ++b)
    #pragma unroll
    for (int c = 0; c < 4; ++c) acc[a][b][c] = 0.f;

    load_stage(0);
    load_stage(1);

    const int arow  = lane & 15;
    const int abyte = (lane >> 4) * 16;
    const int brow  = ((lane >> 4) & 1) * 8 + (lane & 7);
    const int bbyte = ((lane >> 3) & 1) * 16;

    const int S = HID / 64;   // 48
    for (int s = 0; s < S; ++s){
        CP_WAIT(1);
        __syncthreads();
        if (s + 2 < S) load_stage(s + 2);

        uint32_t st = sb + (uint32_t)(s % NST) * STG3;
        #pragma unroll
        for (int ks = 0; ks < 4; ++ks){
            uint32_t ah[2][4], al[2][4];
            #pragma unroll
            for (int mt = 0; mt < 2; ++mt){
                uint32_t aaddr = st + (uint32_t)((wm*32 + mt*16 + arow)*ROWB + ks*32 + abyte);
                ldsm_x4(ah[mt], aaddr + AHI_O);
                ldsm_x4(al[mt], aaddr + ALO_O);
            }
            uint32_t bw[8][2];
            #pragma unroll
            for (int p = 0; p < 4; ++p){
                uint32_t baddr = st + B_O + (uint32_t)((wn*64 + p*16 + brow)*ROWB + ks*32 + bbyte);
                uint32_t t[4];
                ldsm_x4(t, baddr);
                bw[2*p][0]=t[0]; bw[2*p][1]=t[1]; bw[2*p+1][0]=t[2]; bw[2*p+1][1]=t[3];
            }
            #pragma unroll
            for (int mt = 0; mt < 2; ++mt)
            #pragma unroll
            for (int nt = 0; nt < 8; ++nt)
                mma16816(acc[mt][nt], ah[mt], bw[nt]);
            #pragma unroll
            for (int mt = 0; mt < 2; ++mt)
            #pragma unroll
            for (int nt = 0; nt < 8; ++nt)
                mma16816(acc[mt][nt], al[mt], bw[nt]);
        }
    }

    const int g = lane >> 2, tig = lane & 3;
    #pragma unroll
    for (int mt = 0; mt < 2; ++mt){
        int rb = m0 + wm*32 + mt*16 + g;
        #pragma unroll
        for (int nt = 0; nt < 8; ++nt){
            int col = n0 + wn*64 + nt*8 + tig*2;
            #pragma unroll
            for (int rr = 0; rr < 2; ++rr){
                int r = rb + rr*8;
                float2 o;
                o.x = acc[mt][nt][rr*2+0] * FSCALE;
                o.y = acc[mt][nt][rr*2+1] * FSCALE;
                *(float2*)(out + (size_t)r*DIM + col) = o;
            }
        }
    }
}

// ---------------- launch ----------------
extern "C" void kernel_launch(void* const* d_in, const int* in_sizes, int n_in,
                              void* d_out, int out_size)
{
    const float* x  = (const float*)d_in[0];
    const int*   wg = (const int*)d_in[1];
    const int*   wu = (const int*)d_in[2];
    const int*   wd = (const int*)d_in[3];
    float*       out = (float*)d_out;

    const int M = in_sizes[0] / DIM;   // 8192

    __nv_bfloat16 *wgb, *wub, *wdb, *xhi, *xlo, *hhi, *hlo;
    cudaGetSymbolAddress((void**)&wgb, g_wg);
    cudaGetSymbolAddress((void**)&wub, g_wu);
    cudaGetSymbolAddress((void**)&wdb, g_wd);
    cudaGetSymbolAddress((void**)&xhi, g_xhi);
    cudaGetSymbolAddress((void**)&xlo, g_xlo);
    cudaGetSymbolAddress((void**)&hhi, g_hhi);
    cudaGetSymbolAddress((void**)&hlo, g_hlo);

    {
        int n4 = (HID * DIM) / 4;
        k_convw<<<(n4 + 255) / 256, 256>>>(wg, wgb, n4);
        k_convw<<<(n4 + 255) / 256, 256>>>(wu, wub, n4);
        k_convw<<<(n4 + 255) / 256, 256>>>(wd, wdb, n4);
        int nx4 = (M * DIM) / 4;
        k_splitx<<<(nx4 + 255) / 256, 256>>>(x, xhi, xlo, nx4);
    }

    const int SM1 = NST * STG1;   // 221184
    const int SM3 = NST * STG3;   // 221184
    cudaFuncSetAttribute(k_gateup, cudaFuncAttributeMaxDynamicSharedMemorySize, SM1);
    cudaFuncSetAttribute(k_down,   cudaFuncAttributeMaxDynamicSharedMemorySize, SM3);

    dim3 g1(HID / 128, M / 128);   // (24, 64)
    k_gateup<<<g1, 512, SM1>>>(xhi, xlo, wgb, wub, hhi, hlo);

    dim3 g3(DIM / 256, M / 128);   // (4, 64)
    k_down<<<g3, 512, SM3>>>(hhi, hlo, wdb, out);
}

// round 7
// speedup vs baseline: 4.7239x; 1.7269x over previous
#include <cuda_runtime.h>
#include <cuda_fp16.h>
#include <math.h>
#include <stdint.h>

#define DIM  1024
#define HID  3072
#define MTOK 8192
#define FSCALE (1.0f/127.0f)

// ---------------- device scratch ----------------
__device__ __align__(16) __half g_wg[(size_t)HID*DIM];
__device__ __align__(16) __half g_wu[(size_t)HID*DIM];
__device__ __align__(16) __half g_wd[(size_t)DIM*HID];
__device__ __align__(16) __half g_xh[(size_t)MTOK*DIM];
__device__ __align__(16) __half g_h [(size_t)MTOK*HID];

// ---------------- helpers ----------------
__device__ __forceinline__ uint32_t smem_u32(const void* p){
    uint32_t a;
    asm("{ .reg .u64 t; cvta.to.shared.u64 t, %1; cvt.u32.u64 %0, t; }" : "=r"(a) : "l"(p));
    return a;
}
__device__ __forceinline__ void cp_async16(uint32_t s, const void* g){
    asm volatile("cp.async.cg.shared.global [%0], [%1], 16;" :: "r"(s), "l"(g));
}
#define CP_COMMIT() asm volatile("cp.async.commit_group;" ::: "memory")
#define CP_WAIT(N)  asm volatile("cp.async.wait_group %0;" :: "n"(N) : "memory")

__device__ __forceinline__ void ldsm_x4(uint32_t* r, uint32_t a){
    asm volatile("ldmatrix.sync.aligned.m8n8.x4.shared.b16 {%0,%1,%2,%3}, [%4];"
        : "=r"(r[0]),"=r"(r[1]),"=r"(r[2]),"=r"(r[3]) : "r"(a));
}
__device__ __forceinline__ void mma16816(float* d, const uint32_t* a, const uint32_t* b){
    asm volatile("mma.sync.aligned.m16n8k16.row.col.f32.f16.f16.f32 "
        "{%0,%1,%2,%3},{%4,%5,%6,%7},{%8,%9},{%0,%1,%2,%3};"
        : "+f"(d[0]),"+f"(d[1]),"+f"(d[2]),"+f"(d[3])
        : "r"(a[0]),"r"(a[1]),"r"(a[2]),"r"(a[3]), "r"(b[0]),"r"(b[1]));
}

// ---------------- prep kernels ----------------
__global__ void k_convw(const int* __restrict__ w, __half* __restrict__ o, int n4){
    int i = blockIdx.x * blockDim.x + threadIdx.x;
    if (i < n4){
        int4 v = ((const int4*)w)[i];
        __half2 a, b;
        a.x = __float2half((float)v.x); a.y = __float2half((float)v.y);
        b.x = __float2half((float)v.z); b.y = __float2half((float)v.w);
        ((__half2*)o)[2*i]   = a;
        ((__half2*)o)[2*i+1] = b;
    }
}
__global__ void k_castx(const float* __restrict__ x, __half* __restrict__ o, int n4){
    int i = blockIdx.x * blockDim.x + threadIdx.x;
    if (i < n4){
        float4 v = ((const float4*)x)[i];
        __half2 a, b;
        a.x = __float2half(v.x); a.y = __float2half(v.y);
        b.x = __float2half(v.z); b.y = __float2half(v.w);
        ((__half2*)o)[2*i]   = a;
        ((__half2*)o)[2*i+1] = b;
    }
}

// ---------------- GEMM config ----------------
// BK=64 fp16 (128B data rows + 16B pad = 144B stride, conflict-free ldmatrix).
static constexpr int ROWB  = 144;
static constexpr int A_O   = 0;
static constexpr int B_O   = 128*ROWB;          // 18432
static constexpr int BU_O  = 256*ROWB;          // 36864 (Wu in gateup)
static constexpr int STG   = 384*ROWB;          // 55296
static constexpr int NST   = 3;                 // 165888 smem

// ---------------- GEMM1: fused gate/up + SwiGLU -> h fp16 ----------------
// CTA 128m x (128 gate + 128 up), 16 warps 4x4, warp 32 x (32g + 32u).
__global__ __launch_bounds__(512,1)
void k_gateup(const __half* __restrict__ xh,
              const __half* __restrict__ wg, const __half* __restrict__ wu,
              __half* __restrict__ h)
{
    extern __shared__ char sm[];
    const uint32_t sb = smem_u32(sm);
    const int tid = threadIdx.x, lane = tid & 31, wid = tid >> 5;
    const int wm = wid >> 2, wn = wid & 3;
    const int m0 = blockIdx.y * 128, n0 = blockIdx.x * 128;

    // 6 cp.async chunks of 16B per thread per stage (384 rows x 128B)
    const __half* gptr[6];
    uint32_t soff[6];
    #pragma unroll
    for (int j = 0; j < 6; ++j){
        int c = j*512 + tid;          // 0..3071
        int row = c >> 3, seg = c & 7;
        const __half* gp; uint32_t so;
        if (row < 128)      { gp = xh + (size_t)(m0+row)*DIM;     so = A_O  + row*ROWB; }
        else if (row < 256) { gp = wg + (size_t)(n0+row-128)*DIM; so = B_O  + (row-128)*ROWB; }
        else                { gp = wu + (size_t)(n0+row-256)*DIM; so = BU_O + (row-256)*ROWB; }
        gptr[j] = gp + seg*8;
        soff[j] = so + seg*16;
    }
    auto load_stage = [&](int s){
        uint32_t st = sb + (uint32_t)(s % NST) * STG;
        int k0 = s * 64;
        #pragma unroll
        for (int j = 0; j < 6; ++j) cp_async16(st + soff[j], gptr[j] + k0);
        CP_COMMIT();
    };

    float accg[2][4][4], accu[2][4][4];
    #pragma unroll
    for (int a = 0; a < 2; ++a)
    #pragma unroll
    for (int b = 0; b < 4; ++b)
    #pragma unroll
    for (int c = 0; c < 4; ++c){ accg[a][b][c] = 0.f; accu[a][b][c] = 0.f; }

    load_stage(0);
    load_stage(1);

    const int arow  = lane & 15;
    const int abyte = (lane >> 4) * 16;
    const int brow  = ((lane >> 4) & 1) * 8 + (lane & 7);
    const int bbyte = ((lane >> 3) & 1) * 16;

    const int S = DIM / 64;   // 16
    for (int s = 0; s < S; ++s){
        CP_WAIT(1);
        __syncthreads();
        if (s + 2 < S) load_stage(s + 2);

        uint32_t st = sb + (uint32_t)(s % NST) * STG;
        #pragma unroll
        for (int ks = 0; ks < 4; ++ks){
            uint32_t a_[2][4];
            #pragma unroll
            for (int mt = 0; mt < 2; ++mt){
                uint32_t aaddr = st + A_O + (uint32_t)((wm*32 + mt*16 + arow)*ROWB + ks*32 + abyte);
                ldsm_x4(a_[mt], aaddr);
            }
            uint32_t bg[4][2], bu[4][2];
            #pragma unroll
            for (int p = 0; p < 2; ++p){
                uint32_t baddr = st + B_O + (uint32_t)((wn*32 + p*16 + brow)*ROWB + ks*32 + bbyte);
                uint32_t t[4];
                ldsm_x4(t, baddr);
                bg[2*p][0]=t[0]; bg[2*p][1]=t[1]; bg[2*p+1][0]=t[2]; bg[2*p+1][1]=t[3];
                ldsm_x4(t, baddr + (BU_O - B_O));
                bu[2*p][0]=t[0]; bu[2*p][1]=t[1]; bu[2*p+1][0]=t[2]; bu[2*p+1][1]=t[3];
            }
            #pragma unroll
            for (int mt = 0; mt < 2; ++mt)
            #pragma unroll
            for (int nt = 0; nt < 4; ++nt){
                mma16816(accg[mt][nt], a_[mt], bg[nt]);
                mma16816(accu[mt][nt], a_[mt], bu[nt]);
            }
        }
    }

    // epilogue: h = silu(gate)*up -> fp16
    const int g = lane >> 2, tig = lane & 3;
    #pragma unroll
    for (int mt = 0; mt < 2; ++mt){
        int rb = m0 + wm*32 + mt*16 + g;
        #pragma unroll
        for (int nt = 0; nt < 4; ++nt){
            int col = n0 + wn*32 + nt*8 + tig*2;
            #pragma unroll
            for (int rr = 0; rr < 2; ++rr){
                int r = rb + rr*8;
                float g0 = accg[mt][nt][rr*2+0] * FSCALE;
                float g1 = accg[mt][nt][rr*2+1] * FSCALE;
                float u0 = accu[mt][nt][rr*2+0] * FSCALE;
                float u1 = accu[mt][nt][rr*2+1] * FSCALE;
                float h0 = g0 / (1.0f + __expf(-g0)) * u0;
                float h1 = g1 / (1.0f + __expf(-g1)) * u1;
                __half2 ph;
                ph.x = __float2half(h0); ph.y = __float2half(h1);
                *(__half2*)(h + (size_t)r*HID + col) = ph;
            }
        }
    }
}

// ---------------- GEMM3: out = SCALE * h @ Wd^T ----------------
// CTA 128m x 256n, 16 warps 4x4, warp tile 32 x 64. Stage: A 128 + Wd 256 rows.
__global__ __launch_bounds__(512,1)
void k_down(const __half* __restrict__ h, const __half* __restrict__ wd,
            float* __restrict__ out)
{
    extern __shared__ char sm[];
    const uint32_t sb = smem_u32(sm);
    const int tid = threadIdx.x, lane = tid & 31, wid = tid >> 5;
    const int wm = wid >> 2, wn = wid & 3;
    const int m0 = blockIdx.y * 128, n0 = blockIdx.x * 256;

    const __half* gptr[6];
    uint32_t soff[6];
    #pragma unroll
    for (int j = 0; j < 6; ++j){
        int c = j*512 + tid;          // 0..3071
        int row = c >> 3, seg = c & 7;
        const __half* gp; uint32_t so;
        if (row < 128) { gp = h  + (size_t)(m0+row)*HID;     so = A_O + row*ROWB; }
        else           { gp = wd + (size_t)(n0+row-128)*HID; so = B_O + (row-128)*ROWB; }
        gptr[j] = gp + seg*8;
        soff[j] = so + seg*16;
    }
    auto load_stage = [&](int s){
        uint32_t st = sb + (uint32_t)(s % NST) * STG;
        int k0 = s * 64;
        #pragma unroll
        for (int j = 0; j < 6; ++j) cp_async16(st + soff[j], gptr[j] + k0);
        CP_COMMIT();
    };

    float acc[2][8][4];
    #pragma unroll
    for (int a = 0; a < 2; ++a)
    #pragma unroll
    for (int b = 0; b < 8; ++b)
    #pragma unroll
    for (int c = 0; c < 4; ++c) acc[a][b][c] = 0.f;

    load_stage(0);
    load_stage(1);

    const int arow  = lane & 15;
    const int abyte = (lane >> 4) * 16;
    const int brow  = ((lane >> 4) & 1) * 8 + (lane & 7);
    const int bbyte = ((lane >> 3) & 1) * 16;

    const int S = HID / 64;   // 48
    for (int s = 0; s < S; ++s){
        CP_WAIT(1);
        __syncthreads();
        if (s + 2 < S) load_stage(s + 2);

        uint32_t st = sb + (uint32_t)(s % NST) * STG;
        #pragma unroll
        for (int ks = 0; ks < 4; ++ks){
            uint32_t a_[2][4];
            #pragma unroll
            for (int mt = 0; mt < 2; ++mt){
                uint32_t aaddr = st + A_O + (uint32_t)((wm*32 + mt*16 + arow)*ROWB + ks*32 + abyte);
                ldsm_x4(a_[mt], aaddr);
            }
            uint32_t bw[8][2];
            #pragma unroll
            for (int p = 0; p < 4; ++p){
                uint32_t baddr = st + B_O + (uint32_t)((wn*64 + p*16 + brow)*ROWB + ks*32 + bbyte);
                uint32_t t[4];
                ldsm_x4(t, baddr);
                bw[2*p][0]=t[0]; bw[2*p][1]=t[1]; bw[2*p+1][0]=t[2]; bw[2*p+1][1]=t[3];
            }
            #pragma unroll
            for (int mt = 0; mt < 2; ++mt)
            #pragma unroll
            for (int nt = 0; nt < 8; ++nt)
                mma16816(acc[mt][nt], a_[mt], bw[nt]);
        }
    }

    const int g = lane >> 2, tig = lane & 3;
    #pragma unroll
    for (int mt = 0; mt < 2; ++mt){
        int rb = m0 + wm*32 + mt*16 + g;
        #pragma unroll
        for (int nt = 0; nt < 8; ++nt){
            int col = n0 + wn*64 + nt*8 + tig*2;
            #pragma unroll
            for (int rr = 0; rr < 2; ++rr){
                int r = rb + rr*8;
                float2 o;
                o.x = acc[mt][nt][rr*2+0] * FSCALE;
                o.y = acc[mt][nt][rr*2+1] * FSCALE;
                *(float2*)(out + (size_t)r*DIM + col) = o;
            }
        }
    }
}

// ---------------- launch ----------------
extern "C" void kernel_launch(void* const* d_in, const int* in_sizes, int n_in,
                              void* d_out, int out_size)
{
    const float* x  = (const float*)d_in[0];
    const int*   wg = (const int*)d_in[1];
    const int*   wu = (const int*)d_in[2];
    const int*   wd = (const int*)d_in[3];
    float*       out = (float*)d_out;

    const int M = in_sizes[0] / DIM;   // 8192

    __half *wgh, *wuh, *wdh, *xh, *hh;
    cudaGetSymbolAddress((void**)&wgh, g_wg);
    cudaGetSymbolAddress((void**)&wuh, g_wu);
    cudaGetSymbolAddress((void**)&wdh, g_wd);
    cudaGetSymbolAddress((void**)&xh,  g_xh);
    cudaGetSymbolAddress((void**)&hh,  g_h);

    {
        int n4 = (HID * DIM) / 4;
        k_convw<<<(n4 + 255) / 256, 256>>>(wg, wgh, n4);
        k_convw<<<(n4 + 255) / 256, 256>>>(wu, wuh, n4);
        k_convw<<<(n4 + 255) / 256, 256>>>(wd, wdh, n4);
        int nx4 = (M * DIM) / 4;
        k_castx<<<(nx4 + 255) / 256, 256>>>(x, xh, nx4);
    }

    const int SMB = NST * STG;   // 165888
    cudaFuncSetAttribute(k_gateup, cudaFuncAttributeMaxDynamicSharedMemorySize, SMB);
    cudaFuncSetAttribute(k_down,   cudaFuncAttributeMaxDynamicSharedMemorySize, SMB);

    dim3 g1(HID / 128, M / 128);   // (24, 64)
    k_gateup<<<g1, 512, SMB>>>(xh, wgh, wuh, hh);

    dim3 g3(DIM / 256, M / 128);   // (4, 64)
    k_down<<<g3, 512, SMB>>>(hh, wdh, out);
}